// round 7
// baseline (speedup 1.0000x reference)
#include <cuda_runtime.h>
#include <cstdint>

// Batched Thomas tridiagonal solve, B=2048, N=8192, chunked via diagonal
// dominance (alpha in [0,0.3)). Continuant (D/S) recurrence: 1 FMA/step chain,
// rcp.approx off-chain. R6: L=64 chunks (HF=8, HB=28) -> 52.6KB smem/block ->
// 4 blocks/SM (16 warps/SM, 2x occupancy); checkpoints in registers; f loaded
// as broadcast float4 per tile.

#define N_COLSK 8192
#define L_OWN   64
#define HF      8
#define HB      28
#define SPAN_C  101                 // HF + L + HB + 1; odd pitch -> conflict-free LDS
#define TPB     128
#define NT      6                   // tiles: 5 x 16 steps + 1 x 12 steps

#define SM_F    (TPB * SPAN_C)                  // f slice (aligned: 12928 % 4 == 0)
#define SM_DUMP (SM_F + SPAN_C + 3)             // dump slots for masked lanes
#define SMEM_FLOATS (SM_DUMP + TPB)
#define SMEM_BYTES  (SMEM_FLOATS * 4)           // 52,640 B -> 4 blocks/SM

__device__ __forceinline__ float frcp(float x) {
    float r; asm("rcp.approx.f32 %0, %1;" : "=f"(r) : "f"(x)); return r;
}

// cp.async 4B; src_sz = 0 zero-fills the destination (OOB handling).
__device__ __forceinline__ void cpa4(unsigned int saddr, const float* g, int src_sz) {
    asm volatile("cp.async.ca.shared.global [%0], [%1], 4, %2;"
                 :: "r"(saddr), "l"(g), "r"(src_sz));
}

// Phase-2 tile: recompute cp/dp from tile-entry checkpoint, back-substitute.
template<int LEN, bool STORE>
__device__ __forceinline__ void tile_bwd(
    const float* __restrict__ sA, const float* __restrict__ fS, int base,
    float cp_in, float dp_in, float& u, float* __restrict__ op)
{
    float fvv[LEN];
    #pragma unroll
    for (int q = 0; q < LEN / 4; ++q) {          // broadcast LDS.128
        float4 t = reinterpret_cast<const float4*>(fS + base)[q];
        fvv[4*q+0] = t.x; fvv[4*q+1] = t.y; fvv[4*q+2] = t.z; fvv[4*q+3] = t.w;
    }
    float cpl[LEN], dpl[LEN];
    float alm = sA[base - 1];
    float sm1 = alm * alm;                       // a_base
    float a2  = sA[base];
    float qi  = a2 * a2;
    float dmm, dm, sl, qim1;
    {   // j = 0: fold incoming (cp_in, dp_in); local D~_{-1} = 1
        float alp1 = sA[base + 1];
        float sq1  = alp1 * alp1;
        float bi   = fmaf(a2, qi, 1.0f);
        float D0   = fmaf(-sm1, cp_in, bi);
        float S0   = fmaf(-sm1, dp_in, fvv[0]);
        float r    = frcp(D0);
        float cj   = fmaf(2.0f, alp1, sq1);
        cpl[0] = cj * r;
        dpl[0] = S0 * r;
        dmm = 1.0f; dm = D0; sl = S0;
        qim1 = qi; qi = sq1; a2 = alp1;
    }
    #pragma unroll
    for (int j = 1; j < LEN; ++j) {
        float alp1 = sA[base + j + 1];
        float sq1  = alp1 * alp1;
        float bi   = fmaf(a2, qi, 1.0f);
        float cim1 = fmaf(2.0f, a2, qi);
        float t    = (qim1 * cim1) * dmm;
        float dn   = fmaf(bi, dm, -t);
        float sn   = fmaf(-qim1, sl, fvv[j] * dm);
        float r    = frcp(dn);
        float cj   = fmaf(2.0f, alp1, sq1);
        cpl[j] = (cj * dm) * r;
        dpl[j] = sn * r;
        dmm = dm; dm = dn; sl = sn;
        qim1 = qi; qi = sq1; a2 = alp1;
    }
    #pragma unroll
    for (int j = LEN - 1; j >= 0; --j) {
        u = fmaf(-cpl[j], u, dpl[j]);
        dpl[j] = u;
    }
    if (STORE) {
        float4* o4 = reinterpret_cast<float4*>(op);
        #pragma unroll
        for (int q = 0; q < LEN / 4; ++q)
            o4[q] = make_float4(dpl[4*q], dpl[4*q+1], dpl[4*q+2], dpl[4*q+3]);
    }
}

__global__ __launch_bounds__(TPB, 4)
void thomas_chunk_kernel(const float* __restrict__ alpha,
                         const float* __restrict__ f,
                         float* __restrict__ out)
{
    extern __shared__ float smem[];
    float* fS = smem + SM_F;

    const int tid  = threadIdx.x;
    const int cc   = blockIdx.x;                 // chunk column (0..127)
    const int row0 = blockIdx.y * TPB;
    const int s    = cc * L_OWN;
    const int col0 = s - HF;                     // first staged col (>= -8)

    // ================= cp.async staging (1 col/lane, 128 rows) =================
    {
        const unsigned int smb  = (unsigned int)__cvta_generic_to_shared(smem);
        const unsigned int dump = smb + (unsigned int)(SM_DUMP + tid) * 4u;

        const bool act = tid < SPAN_C;
        const int  c1  = col0 + tid;
        const int  sz1 = (act && c1 >= 0 && c1 < N_COLSK) ? 4 : 0;
        const int  c1c = max(0, min(c1, N_COLSK - 1));

        const float* g1 = alpha + (size_t)row0 * N_COLSK + c1c;
        unsigned int s1 = act ? (smb + (unsigned int)tid * 4u) : dump;
        const unsigned int step = act ? (SPAN_C * 4u) : 0u;

        #pragma unroll 4
        for (int r = 0; r < TPB; ++r) {
            cpa4(s1, g1, sz1);
            s1 += step; g1 += N_COLSK;
        }
        cpa4(act ? (smb + (unsigned int)(SM_F + tid) * 4u) : dump, f + c1c, sz1);

        asm volatile("cp.async.commit_group;");
        asm volatile("cp.async.wait_group 0;");
    }
    __syncthreads();

    const float* sA = smem + tid * SPAN_C;

    // ================= phase 1: forward continuant sweep =================
    float Dmm = 0.0f, Dm = 1.0f, S = 0.0f;
    float sqim1 = 0.0f;
    float al  = sA[0];
    float sqi = al * al;
    float ckcp[NT], ckdp[NT];

#define FSTEP(RC, FV) do {                               \
        float alp1 = sA[(RC) + 1];                       \
        float sq1  = alp1 * alp1;                        \
        float bi   = fmaf(al, sqi, 1.0f);                \
        float cim1 = fmaf(2.0f, al, sqi);                \
        float t    = (sqim1 * cim1) * Dmm;               \
        float Dn   = fmaf(bi, Dm, -t);                   \
        float Sn   = fmaf(-sqim1, S, (FV) * Dm);         \
        Dmm = Dm; Dm = Dn; S = Sn;                       \
        sqim1 = sqi; sqi = sq1; al = alp1;               \
    } while (0)

    {   // warmup over left halo (8 steps), f via 2 broadcast float4s
        float4 f0 = reinterpret_cast<const float4*>(fS)[0];
        float4 f1 = reinterpret_cast<const float4*>(fS)[1];
        float fv[8] = {f0.x, f0.y, f0.z, f0.w, f1.x, f1.y, f1.z, f1.w};
        #pragma unroll
        for (int j = 0; j < 8; ++j) FSTEP(j, fv[j]);
    }

    #pragma unroll
    for (int k = 0; k < 5; ++k) {                // forward through tiles 0..4
        float r    = frcp(Dm);
        float cim1 = fmaf(2.0f, al, sqi);        // c_{base-1}
        ckcp[k] = (cim1 * Dmm) * r;
        ckdp[k] = S * r;
        const int base = HF + (k << 4);
        float fv[16];
        #pragma unroll
        for (int q = 0; q < 4; ++q) {
            float4 t = reinterpret_cast<const float4*>(fS + base)[q];
            fv[4*q+0] = t.x; fv[4*q+1] = t.y; fv[4*q+2] = t.z; fv[4*q+3] = t.w;
        }
        #pragma unroll
        for (int j = 0; j < 16; ++j) FSTEP(base + j, fv[j]);
    }
    {   // checkpoint for tile 5 (its forward steps are recomputed in phase 2)
        float r    = frcp(Dm);
        float cim1 = fmaf(2.0f, al, sqi);
        ckcp[5] = (cim1 * Dmm) * r;
        ckdp[5] = S * r;
    }
#undef FSTEP

    // ================= phase 2: tiles descending, back-substitution =========
    float u = 0.0f;                              // halo cut at top
    float* ob = out + (size_t)(row0 + tid) * N_COLSK + s;

    tile_bwd<12, false>(sA, fS, HF + 80, ckcp[5], ckdp[5], u, nullptr);
    tile_bwd<16, false>(sA, fS, HF + 64, ckcp[4], ckdp[4], u, nullptr);
    tile_bwd<16, true >(sA, fS, HF + 48, ckcp[3], ckdp[3], u, ob + 48);
    tile_bwd<16, true >(sA, fS, HF + 32, ckcp[2], ckdp[2], u, ob + 32);
    tile_bwd<16, true >(sA, fS, HF + 16, ckcp[1], ckdp[1], u, ob + 16);
    tile_bwd<16, true >(sA, fS, HF +  0, ckcp[0], ckdp[0], u, ob);
}

extern "C" void kernel_launch(void* const* d_in, const int* in_sizes, int n_in,
                              void* d_out, int out_size)
{
    const float* alpha = (const float*)d_in[0];
    const float* f     = (const float*)d_in[1];
    float* out         = (float*)d_out;

    static int smem_set = 0;
    if (!smem_set) {
        cudaFuncSetAttribute(thomas_chunk_kernel,
                             cudaFuncAttributeMaxDynamicSharedMemorySize,
                             SMEM_BYTES);
        smem_set = 1;
    }

    dim3 grid(N_COLSK / L_OWN, 2048 / TPB);      // (128, 16)
    thomas_chunk_kernel<<<grid, TPB, SMEM_BYTES>>>(alpha, f, out);
}